// round 3
// baseline (speedup 1.0000x reference)
#include <cuda_runtime.h>
#include <cstddef>

#define D128 128
#define NFEAT 10
#define N_IP 20000
#define N_CONN 100000
#define N_E 200000
#define T_ITERS 3

// ---------------- scratch (static device globals; no allocation) ----------------
__device__ float g_ip[N_IP * D128];          // ip_state
__device__ float g_conn[N_CONN * D128];      // connection_state
__device__ float g_XA[N_IP * D128];          // ip @ W_m1_top
__device__ float g_XB[N_CONN * D128];        // conn @ W_m1_bot
__device__ float g_YA[N_CONN * D128];        // conn @ W_m2_top
__device__ float g_YB[N_IP * D128];          // ip @ W_m2_bot
__device__ float g_agg_conn[N_CONN * D128];  // sum of ip->conn messages (per connection)
__device__ float g_agg_ip[N_IP * D128];      // sum of conn->ip messages (per ip)
__device__ float g_xm_ip[N_IP * 384];
__device__ float g_hm_ip[N_IP * 384];
__device__ float g_xm_c[N_CONN * 384];
__device__ float g_hm_c[N_CONN * 384];
__device__ float g_rc_conn[N_CONN];          // 1/max(indeg,1) per connection
__device__ float g_rc_ip[N_IP];              // 1/max(indeg,1) per ip
__device__ float g_H1[N_CONN * D128];
__device__ float g_H2[N_CONN * 64];

// ---------------- small utility kernels ----------------
__global__ void fill_kernel(float* __restrict__ p, int n4, float v) {
    int i = blockIdx.x * blockDim.x + threadIdx.x;
    if (i < n4) *(float4*)(p + (size_t)i * 4) = make_float4(v, v, v, v);
}

__global__ void init_conn_kernel(float* __restrict__ p, const float* __restrict__ feat) {
    int i = blockIdx.x * blockDim.x + threadIdx.x;
    if (i < N_CONN * D128) {
        int r = i >> 7;
        int c = i & 127;
        p[i] = (c < NFEAT) ? feat[r * NFEAT + c] : 0.f;
    }
}

__global__ void count_kernel(const int* __restrict__ dst, float* __restrict__ cnt, int e) {
    int i = blockIdx.x * blockDim.x + threadIdx.x;
    if (i < e) atomicAdd(cnt + dst[i], 1.f);
}

__global__ void recip_kernel(float* __restrict__ c, int n) {
    int i = blockIdx.x * blockDim.x + threadIdx.x;
    if (i < n) c[i] = 1.f / fmaxf(c[i], 1.f);
}

// ---------------- SGEMM: C[MxN] = act( rowscale(A[Mx128]) @ B[128xN] + bias ) ----------------
// BM=BN=64, 256 threads, 4x4 microtile, K=128 fixed (lda = 128).
__global__ __launch_bounds__(256) void sgemm_k128(
    const float* __restrict__ A, const float* __restrict__ B, float* __restrict__ C,
    int M, int N, const float* __restrict__ bias, const float* __restrict__ rscale,
    int do_relu)
{
    __shared__ float As[64][68];  // As[k][m]
    __shared__ float Bs[64][68];  // Bs[k][n]

    const int bm = blockIdx.y * 64;
    const int bn = blockIdx.x * 64;
    const int tid = threadIdx.x;
    const int tx = tid & 15;   // n-dir
    const int ty = tid >> 4;   // m-dir

    float acc[4][4];
#pragma unroll
    for (int i = 0; i < 4; i++)
#pragma unroll
        for (int j = 0; j < 4; j++) acc[i][j] = 0.f;

    for (int k0 = 0; k0 < 128; k0 += 64) {
        // Load A tile (64 rows x 64 k), transposed into As[k][m]
#pragma unroll
        for (int i = 0; i < 4; i++) {
            int l = tid + i * 256;          // 0..1023
            int r = l >> 4;                 // tile row 0..63
            int c = (l & 15) << 2;          // tile k 0..60
            int grow = bm + r;
            float4 v = make_float4(0.f, 0.f, 0.f, 0.f);
            if (grow < M) {
                v = *(const float4*)(A + (size_t)grow * 128 + k0 + c);
                if (rscale) {
                    float s = rscale[grow];
                    v.x *= s; v.y *= s; v.z *= s; v.w *= s;
                }
            }
            As[c + 0][r] = v.x;
            As[c + 1][r] = v.y;
            As[c + 2][r] = v.z;
            As[c + 3][r] = v.w;
        }
        // Load B tile (64 k x 64 n): B is [128 x N], full K always present
#pragma unroll
        for (int i = 0; i < 4; i++) {
            int l = tid + i * 256;
            int r = l >> 4;
            int c = (l & 15) << 2;
            float4 v = *(const float4*)(B + (size_t)(k0 + r) * N + bn + c);
            *(float4*)(&Bs[r][c]) = v;
        }
        __syncthreads();

#pragma unroll
        for (int k = 0; k < 64; k++) {
            float4 a = *(const float4*)(&As[k][ty << 2]);
            float4 b = *(const float4*)(&Bs[k][tx << 2]);
            acc[0][0] += a.x * b.x; acc[0][1] += a.x * b.y; acc[0][2] += a.x * b.z; acc[0][3] += a.x * b.w;
            acc[1][0] += a.y * b.x; acc[1][1] += a.y * b.y; acc[1][2] += a.y * b.z; acc[1][3] += a.y * b.w;
            acc[2][0] += a.z * b.x; acc[2][1] += a.z * b.y; acc[2][2] += a.z * b.z; acc[2][3] += a.z * b.w;
            acc[3][0] += a.w * b.x; acc[3][1] += a.w * b.y; acc[3][2] += a.w * b.z; acc[3][3] += a.w * b.w;
        }
        __syncthreads();
    }

    int gc = bn + (tx << 2);
    float4 bv = make_float4(0.f, 0.f, 0.f, 0.f);
    if (bias) bv = *(const float4*)(bias + gc);
#pragma unroll
    for (int i = 0; i < 4; i++) {
        int gr = bm + (ty << 2) + i;
        if (gr < M) {
            float4 o;
            o.x = acc[i][0] + bv.x;
            o.y = acc[i][1] + bv.y;
            o.z = acc[i][2] + bv.z;
            o.w = acc[i][3] + bv.w;
            if (do_relu) {
                o.x = fmaxf(o.x, 0.f); o.y = fmaxf(o.y, 0.f);
                o.z = fmaxf(o.z, 0.f); o.w = fmaxf(o.w, 0.f);
            }
            *(float4*)(C + (size_t)gr * N + gc) = o;
        }
    }
}

// ---------------- edge message + scatter-add: sum[dst] += relu(XS[src] + XD[dst] + bias) ----------------
// one warp per edge, float4 per lane (128 floats / edge)
__global__ void edge_msg_kernel(
    const int* __restrict__ src, const int* __restrict__ dst,
    const float* __restrict__ XS, const float* __restrict__ XD,
    const float* __restrict__ bias, float* __restrict__ out_sum, int e)
{
    int gw = (blockIdx.x * blockDim.x + threadIdx.x) >> 5;
    if (gw >= e) return;
    int lane = threadIdx.x & 31;
    int s = __ldg(src + gw);
    int d = __ldg(dst + gw);
    int c = lane << 2;
    float4 a = *(const float4*)(XS + (size_t)s * 128 + c);
    float4 b = *(const float4*)(XD + (size_t)d * 128 + c);
    float4 bb = *(const float4*)(bias + c);
    float4 m;
    m.x = fmaxf(a.x + b.x + bb.x, 0.f);
    m.y = fmaxf(a.y + b.y + bb.y, 0.f);
    m.z = fmaxf(a.z + b.z + bb.z, 0.f);
    m.w = fmaxf(a.w + b.w + bb.w, 0.f);
    float* p = out_sum + (size_t)d * 128 + c;
    atomicAdd(p + 0, m.x);
    atomicAdd(p + 1, m.y);
    atomicAdd(p + 2, m.z);
    atomicAdd(p + 3, m.w);
}

// ---------------- GRU gate fusion (keras reset_after=True, gate order [z,r,hh]) ----------------
__device__ __forceinline__ float gru1(float xz, float hz, float xr, float hr,
                                      float xh, float hh, float h) {
    float z = 1.f / (1.f + expf(-(xz + hz)));
    float r = 1.f / (1.f + expf(-(xr + hr)));
    float c = tanhf(xh + r * hh);
    return z * h + (1.f - z) * c;
}

__global__ void gru_gate_kernel(float* __restrict__ h, const float* __restrict__ xm,
                                const float* __restrict__ hm, int M)
{
    int idx = blockIdx.x * blockDim.x + threadIdx.x;
    if (idx >= M * 32) return;
    int row = idx >> 5;
    int c = (idx & 31) << 2;
    const float* x = xm + (size_t)row * 384;
    const float* hh = hm + (size_t)row * 384;
    float4 xz = *(const float4*)(x + c);
    float4 xr = *(const float4*)(x + 128 + c);
    float4 xh = *(const float4*)(x + 256 + c);
    float4 hz = *(const float4*)(hh + c);
    float4 hr = *(const float4*)(hh + 128 + c);
    float4 hc = *(const float4*)(hh + 256 + c);
    float* hp = h + (size_t)row * 128 + c;
    float4 hv = *(const float4*)hp;
    float4 o;
    o.x = gru1(xz.x, hz.x, xr.x, hr.x, xh.x, hc.x, hv.x);
    o.y = gru1(xz.y, hz.y, xr.y, hr.y, xh.y, hc.y, hv.y);
    o.z = gru1(xz.z, hz.z, xr.z, hr.z, xh.z, hc.z, hv.z);
    o.w = gru1(xz.w, hz.w, xr.w, hr.w, xh.w, hc.w, hv.w);
    *(float4*)hp = o;
}

// ---------------- readout tail: out = softmax(H2[Mx64] @ W3[64x15] + b3) ----------------
__global__ void readout_kernel(const float* __restrict__ H2, const float* __restrict__ W3,
                               const float* __restrict__ b3, float* __restrict__ out, int M)
{
    __shared__ float w[64 * 15];
    __shared__ float bb[15];
    for (int i = threadIdx.x; i < 64 * 15; i += blockDim.x) w[i] = W3[i];
    if (threadIdx.x < 15) bb[threadIdx.x] = b3[threadIdx.x];
    __syncthreads();

    int row = blockIdx.x * blockDim.x + threadIdx.x;
    if (row >= M) return;

    float acc[15];
#pragma unroll
    for (int j = 0; j < 15; j++) acc[j] = bb[j];
    const float* hrow = H2 + (size_t)row * 64;
#pragma unroll 16
    for (int k = 0; k < 64; k++) {
        float hv = __ldg(hrow + k);
#pragma unroll
        for (int j = 0; j < 15; j++) acc[j] += hv * w[k * 15 + j];
    }
    float mx = acc[0];
#pragma unroll
    for (int j = 1; j < 15; j++) mx = fmaxf(mx, acc[j]);
    float sum = 0.f;
#pragma unroll
    for (int j = 0; j < 15; j++) { acc[j] = expf(acc[j] - mx); sum += acc[j]; }
    float inv = 1.f / sum;
    float* op = out + (size_t)row * 15;
#pragma unroll
    for (int j = 0; j < 15; j++) op[j] = acc[j] * inv;
}

// ---------------- host side ----------------
static inline void launch_gemm(const float* A, const float* B, float* C, int M, int N,
                               const float* bias, const float* rs, int relu) {
    dim3 grid(N / 64, (M + 63) / 64);
    sgemm_k128<<<grid, 256>>>(A, B, C, M, N, bias, rs, relu);
}

static inline void launch_zero(float* p, int n) {  // n multiple of 4
    int n4 = n >> 2;
    fill_kernel<<<(n4 + 255) / 256, 256>>>(p, n4, 0.f);
}

extern "C" void kernel_launch(void* const* d_in, const int* in_sizes, int n_in,
                              void* d_out, int out_size)
{
    const float* feat  = (const float*)d_in[0];
    const int*   s_i2c = (const int*)d_in[1];   // src_ip_to_connection (ip ids)
    const int*   d_i2c = (const int*)d_in[2];   // dst_ip_to_connection (conn ids)
    const int*   s_c2i = (const int*)d_in[3];   // src_connection_to_ip (conn ids)
    const int*   d_c2i = (const int*)d_in[4];   // dst_connection_to_ip (ip ids)
    const float* W_m1  = (const float*)d_in[5];
    const float* b_m1  = (const float*)d_in[6];
    const float* W_m2  = (const float*)d_in[7];
    const float* b_m2  = (const float*)d_in[8];
    const float* gik   = (const float*)d_in[9];
    const float* gir   = (const float*)d_in[10];
    const float* gib   = (const float*)d_in[11];
    const float* gck   = (const float*)d_in[12];
    const float* gcr   = (const float*)d_in[13];
    const float* gcb   = (const float*)d_in[14];
    const float* Wr1   = (const float*)d_in[15];
    const float* br1   = (const float*)d_in[16];
    const float* Wr2   = (const float*)d_in[17];
    const float* br2   = (const float*)d_in[18];
    const float* Wr3   = (const float*)d_in[19];
    const float* br3   = (const float*)d_in[20];
    float* out = (float*)d_out;

    void* p;
    cudaGetSymbolAddress(&p, g_ip);       float* ip       = (float*)p;
    cudaGetSymbolAddress(&p, g_conn);     float* conn     = (float*)p;
    cudaGetSymbolAddress(&p, g_XA);       float* XA       = (float*)p;
    cudaGetSymbolAddress(&p, g_XB);       float* XB       = (float*)p;
    cudaGetSymbolAddress(&p, g_YA);       float* YA       = (float*)p;
    cudaGetSymbolAddress(&p, g_YB);       float* YB       = (float*)p;
    cudaGetSymbolAddress(&p, g_agg_conn); float* agg_conn = (float*)p;
    cudaGetSymbolAddress(&p, g_agg_ip);   float* agg_ip   = (float*)p;
    cudaGetSymbolAddress(&p, g_xm_ip);    float* xm_ip    = (float*)p;
    cudaGetSymbolAddress(&p, g_hm_ip);    float* hm_ip    = (float*)p;
    cudaGetSymbolAddress(&p, g_xm_c);     float* xm_c     = (float*)p;
    cudaGetSymbolAddress(&p, g_hm_c);     float* hm_c     = (float*)p;
    cudaGetSymbolAddress(&p, g_rc_conn);  float* rc_conn  = (float*)p;
    cudaGetSymbolAddress(&p, g_rc_ip);    float* rc_ip    = (float*)p;
    cudaGetSymbolAddress(&p, g_H1);       float* H1       = (float*)p;
    cudaGetSymbolAddress(&p, g_H2);       float* H2       = (float*)p;

    // --- segment counts (reciprocals), recomputed every call (deterministic work) ---
    launch_zero(rc_conn, N_CONN);
    launch_zero(rc_ip, N_IP);
    count_kernel<<<(N_E + 255) / 256, 256>>>(d_i2c, rc_conn, N_E);
    count_kernel<<<(N_E + 255) / 256, 256>>>(d_c2i, rc_ip, N_E);
    recip_kernel<<<(N_CONN + 255) / 256, 256>>>(rc_conn, N_CONN);
    recip_kernel<<<(N_IP + 255) / 256, 256>>>(rc_ip, N_IP);

    // --- init states ---
    fill_kernel<<<((N_IP * D128 / 4) + 255) / 256, 256>>>(ip, N_IP * D128 / 4, 1.f);
    init_conn_kernel<<<(N_CONN * D128 + 255) / 256, 256>>>(conn, feat);

    const int edge_blocks = (N_E * 32 + 255) / 256;

    for (int t = 0; t < T_ITERS; t++) {
        // Per-node halves of the message MLPs (factorized concat-GEMM)
        launch_gemm(ip,   W_m1,              XA, N_IP,   128, nullptr, nullptr, 0);
        launch_gemm(conn, W_m1 + 128 * 128,  XB, N_CONN, 128, nullptr, nullptr, 0);
        launch_gemm(conn, W_m2,              YA, N_CONN, 128, nullptr, nullptr, 0);
        launch_gemm(ip,   W_m2 + 128 * 128,  YB, N_IP,   128, nullptr, nullptr, 0);

        launch_zero(agg_conn, N_CONN * D128);
        launch_zero(agg_ip, N_IP * D128);

        // ip->connection messages, aggregated per connection
        edge_msg_kernel<<<edge_blocks, 256>>>(s_i2c, d_i2c, XA, XB, b_m1, agg_conn, N_E);
        // connection->ip messages, aggregated per ip
        edge_msg_kernel<<<edge_blocks, 256>>>(s_c2i, d_c2i, YA, YB, b_m2, agg_ip, N_E);

        // GRU pre-activations (mean folded in via row-scale on the sum)
        launch_gemm(agg_ip,   gik, xm_ip, N_IP,   384, gib,       rc_ip,   0);
        launch_gemm(ip,       gir, hm_ip, N_IP,   384, gib + 384, nullptr, 0);
        launch_gemm(agg_conn, gck, xm_c,  N_CONN, 384, gcb,       rc_conn, 0);
        launch_gemm(conn,     gcr, hm_c,  N_CONN, 384, gcb + 384, nullptr, 0);

        // GRU gate updates (in place)
        gru_gate_kernel<<<(N_IP * 32 + 255) / 256, 256>>>(ip, xm_ip, hm_ip, N_IP);
        gru_gate_kernel<<<(N_CONN * 32 + 255) / 256, 256>>>(conn, xm_c, hm_c, N_CONN);
    }

    // --- readout ---
    launch_gemm(conn, Wr1, H1, N_CONN, 128, br1, nullptr, 1);
    launch_gemm(H1,  Wr2, H2, N_CONN, 64,  br2, nullptr, 1);
    readout_kernel<<<(N_CONN + 127) / 128, 128>>>(H2, Wr3, br3, out, N_CONN);
}

// round 5
// speedup vs baseline: 1.6795x; 1.6795x over previous
#include <cuda_runtime.h>
#include <cuda_bf16.h>
#include <cstdint>
#include <cstddef>

#define D128 128
#define NFEAT 10
#define N_IP 20000
#define N_CONN 100000
#define N_E 200000
#define T_ITERS 3

// ---------------- scratch (static device globals; no allocation) ----------------
__device__ float g_ip[N_IP * D128];
__device__ float g_conn[N_CONN * D128];
__device__ float g_XA[N_IP * D128];
__device__ float g_XB[N_CONN * D128];
__device__ float g_YA[N_CONN * D128];
__device__ float g_YB[N_IP * D128];
__device__ float g_agg_conn[N_CONN * D128];
__device__ float g_agg_ip[N_IP * D128];
__device__ float g_xm_ip[N_IP * 384];
__device__ float g_hm_ip[N_IP * 384];
__device__ float g_xm_c[N_CONN * 384];
__device__ float g_hm_c[N_CONN * 384];
__device__ float g_rc_conn[N_CONN];
__device__ float g_rc_ip[N_IP];
__device__ float g_H1[N_CONN * D128];
__device__ float g_H2[N_CONN * 64];

// bf16 hi/lo split, transposed weights [N][128]
__device__ __nv_bfloat16 g_m1t_h[128 * 128], g_m1t_l[128 * 128];
__device__ __nv_bfloat16 g_m1b_h[128 * 128], g_m1b_l[128 * 128];
__device__ __nv_bfloat16 g_m2t_h[128 * 128], g_m2t_l[128 * 128];
__device__ __nv_bfloat16 g_m2b_h[128 * 128], g_m2b_l[128 * 128];
__device__ __nv_bfloat16 g_gik_h[384 * 128], g_gik_l[384 * 128];
__device__ __nv_bfloat16 g_gir_h[384 * 128], g_gir_l[384 * 128];
__device__ __nv_bfloat16 g_gck_h[384 * 128], g_gck_l[384 * 128];
__device__ __nv_bfloat16 g_gcr_h[384 * 128], g_gcr_l[384 * 128];
__device__ __nv_bfloat16 g_wr1_h[128 * 128], g_wr1_l[128 * 128];
__device__ __nv_bfloat16 g_wr2_h[64 * 128],  g_wr2_l[64 * 128];

// ---------------- helpers ----------------
__device__ __forceinline__ uint32_t smem_u32(const void* p) {
    uint32_t a;
    asm("{ .reg .u64 t; cvta.to.shared.u64 t, %1; cvt.u32.u64 %0, t; }" : "=r"(a) : "l"(p));
    return a;
}
__device__ __forceinline__ void ldsm_x4(uint32_t& r0, uint32_t& r1, uint32_t& r2, uint32_t& r3,
                                        uint32_t addr) {
    asm volatile("ldmatrix.sync.aligned.m8n8.x4.shared.b16 {%0,%1,%2,%3}, [%4];"
                 : "=r"(r0), "=r"(r1), "=r"(r2), "=r"(r3) : "r"(addr));
}
__device__ __forceinline__ void mma16816(float* c, const uint32_t* a, const uint32_t* b) {
    asm volatile(
        "mma.sync.aligned.m16n8k16.row.col.f32.bf16.bf16.f32 "
        "{%0,%1,%2,%3}, {%4,%5,%6,%7}, {%8,%9}, {%0,%1,%2,%3};"
        : "+f"(c[0]), "+f"(c[1]), "+f"(c[2]), "+f"(c[3])
        : "r"(a[0]), "r"(a[1]), "r"(a[2]), "r"(a[3]), "r"(b[0]), "r"(b[1]));
}
__device__ __forceinline__ uint32_t pack_bf2(__nv_bfloat16 a, __nv_bfloat16 b) {
    return ((uint32_t)__bfloat16_as_ushort(b) << 16) | (uint32_t)__bfloat16_as_ushort(a);
}

// ---------------- HMMA GEMM: C[MxNtot] = act(rowscale(A[Mx128]) @ Wt^T + bias) ----------------
// Wt (Bh/Bl) = [Ntot x 128] transposed weight in bf16 hi/lo.
// fp32-ish accuracy: acc += Ah*Bh + Ah*Bl + Al*Bh (fp32 register accumulators).
// Block tile 128 x NTILE, 256 threads. SMEM: A hi/lo (64KB) + B hi/lo (NTILE*512 B).
// Swizzle: row r (256B of bf16), 16B chunk kc -> phys chunk kc ^ (r&7) (conflict-free ldmatrix).
template <int NTILE>
__global__ __launch_bounds__(256) void mma_gemm(
    const float* __restrict__ A, const __nv_bfloat16* __restrict__ Bh,
    const __nv_bfloat16* __restrict__ Bl, float* __restrict__ C,
    int M, int ldc, const float* __restrict__ bias,
    const float* __restrict__ rscale, int do_relu)
{
    constexpr int WM = (NTILE == 128) ? 64 : 32;   // warp tile rows
    constexpr int MT = WM / 16;                    // m16 tiles per warp
    constexpr int A_HI = 0, A_LO = 32768, B_HI = 65536;
    constexpr int B_LO = B_HI + NTILE * 256;

    extern __shared__ char smem[];
    const uint32_t sb = smem_u32(smem);
    const int tid = threadIdx.x, wid = tid >> 5, lane = tid & 31;
    const int m0 = blockIdx.x * 128;
    const int col0 = blockIdx.y * NTILE;
    int wm, wn;
    if (NTILE == 128) { wm = wid & 1; wn = wid >> 1; }   // 2x4 warp grid
    else              { wm = wid & 3; wn = wid >> 2; }   // 4x2 warp grid

    // ---- fill A: fp32 -> bf16 hi/lo, swizzled ----
#pragma unroll
    for (int i = 0; i < 8; i++) {
        int idx = tid + i * 256;
        int r = idx >> 4, kc = idx & 15;       // row 0..127, 16B chunk 0..15 (k = kc*8)
        int gr = m0 + r;
        float4 v0 = make_float4(0.f, 0.f, 0.f, 0.f), v1 = v0;
        if (gr < M) {
            const float* ap = A + (size_t)gr * 128 + kc * 8;
            v0 = *(const float4*)ap;
            v1 = *(const float4*)(ap + 4);
            if (rscale) {
                float s = rscale[gr];
                v0.x *= s; v0.y *= s; v0.z *= s; v0.w *= s;
                v1.x *= s; v1.y *= s; v1.z *= s; v1.w *= s;
            }
        }
        float f[8] = {v0.x, v0.y, v0.z, v0.w, v1.x, v1.y, v1.z, v1.w};
        uint32_t hw[4], lw[4];
#pragma unroll
        for (int j = 0; j < 4; j++) {
            __nv_bfloat16 h0 = __float2bfloat16(f[2 * j]);
            __nv_bfloat16 h1 = __float2bfloat16(f[2 * j + 1]);
            __nv_bfloat16 l0 = __float2bfloat16(f[2 * j] - __bfloat162float(h0));
            __nv_bfloat16 l1 = __float2bfloat16(f[2 * j + 1] - __bfloat162float(h1));
            hw[j] = pack_bf2(h0, h1);
            lw[j] = pack_bf2(l0, l1);
        }
        uint32_t sw = (uint32_t)(r * 256 + ((kc ^ (r & 7)) << 4));
        *(uint4*)(smem + A_HI + sw) = make_uint4(hw[0], hw[1], hw[2], hw[3]);
        *(uint4*)(smem + A_LO + sw) = make_uint4(lw[0], lw[1], lw[2], lw[3]);
    }
    // ---- fill B: copy pre-split bf16 [NTILE x 128], swizzled ----
#pragma unroll
    for (int i = 0; i < NTILE / 16; i++) {
        int idx = tid + i * 256;
        int r = idx >> 4, kc = idx & 15;
        uint32_t sw = (uint32_t)(r * 256 + ((kc ^ (r & 7)) << 4));
        *(uint4*)(smem + B_HI + sw) = ((const uint4*)(Bh + (size_t)(col0 + r) * 128))[kc];
        *(uint4*)(smem + B_LO + sw) = ((const uint4*)(Bl + (size_t)(col0 + r) * 128))[kc];
    }
    __syncthreads();

    // ---- mainloop ----
    float acc[MT][4][4];
#pragma unroll
    for (int mt = 0; mt < MT; mt++)
#pragma unroll
        for (int nt = 0; nt < 4; nt++)
#pragma unroll
            for (int j = 0; j < 4; j++) acc[mt][nt][j] = 0.f;

    // ldmatrix per-lane row/chunk selectors
    const int rA = ((lane >> 3) & 1) * 8 + (lane & 7);  // row within 16-row tile
    const int cA = lane >> 4;                           // k-half select
    const int rB = ((lane >> 4) << 3) + (lane & 7);     // row within 16-n pair
    const int cB = (lane >> 3) & 1;

#pragma unroll
    for (int ks = 0; ks < 8; ks++) {
        const int kc0 = ks * 2;
        uint32_t ah[MT][4], al[MT][4], bh[4][2], bl[4][2];
#pragma unroll
        for (int mt = 0; mt < MT; mt++) {
            int row = wm * WM + mt * 16 + rA;
            uint32_t ad = sb + A_HI + row * 256 + (((kc0 + cA) ^ (row & 7)) << 4);
            ldsm_x4(ah[mt][0], ah[mt][1], ah[mt][2], ah[mt][3], ad);
            ldsm_x4(al[mt][0], al[mt][1], al[mt][2], al[mt][3], ad + (A_LO - A_HI));
        }
#pragma unroll
        for (int p = 0; p < 2; p++) {
            int row = wn * 32 + p * 16 + rB;
            uint32_t bd = sb + B_HI + row * 256 + (((kc0 + cB) ^ (row & 7)) << 4);
            uint32_t r0, r1, r2, r3;
            ldsm_x4(r0, r1, r2, r3, bd);
            bh[p * 2][0] = r0; bh[p * 2][1] = r1; bh[p * 2 + 1][0] = r2; bh[p * 2 + 1][1] = r3;
            ldsm_x4(r0, r1, r2, r3, bd + (B_LO - B_HI));
            bl[p * 2][0] = r0; bl[p * 2][1] = r1; bl[p * 2 + 1][0] = r2; bl[p * 2 + 1][1] = r3;
        }
#pragma unroll
        for (int mt = 0; mt < MT; mt++)
#pragma unroll
            for (int nt = 0; nt < 4; nt++) {
                mma16816(acc[mt][nt], ah[mt], bh[nt]);
                mma16816(acc[mt][nt], ah[mt], bl[nt]);
                mma16816(acc[mt][nt], al[mt], bh[nt]);
            }
    }

    // ---- epilogue ----
    const int rowg = lane >> 2, colg = (lane & 3) * 2;
#pragma unroll
    for (int mt = 0; mt < MT; mt++) {
#pragma unroll
        for (int nt = 0; nt < 4; nt++) {
            int gc = col0 + wn * 32 + nt * 8 + colg;
            float bx = 0.f, by = 0.f;
            if (bias) { bx = __ldg(bias + gc); by = __ldg(bias + gc + 1); }
#pragma unroll
            for (int h = 0; h < 2; h++) {
                int gr = m0 + wm * WM + mt * 16 + h * 8 + rowg;
                if (gr < M) {
                    float x = acc[mt][nt][h * 2 + 0] + bx;
                    float y = acc[mt][nt][h * 2 + 1] + by;
                    if (do_relu) { x = fmaxf(x, 0.f); y = fmaxf(y, 0.f); }
                    float2 o; o.x = x; o.y = y;
                    *(float2*)(C + (size_t)gr * ldc + gc) = o;
                }
            }
        }
    }
}

// ---------------- weight prep: W[128 x N] -> transposed bf16 hi/lo [N x 128] ----------------
__global__ void prep_weight(const float* __restrict__ W, int N,
                            __nv_bfloat16* __restrict__ hi, __nv_bfloat16* __restrict__ lo)
{
    int idx = blockIdx.x * blockDim.x + threadIdx.x;
    if (idx >= N * 128) return;
    int n = idx >> 7, k = idx & 127;
    float x = W[(size_t)k * N + n];
    __nv_bfloat16 h = __float2bfloat16(x);
    hi[idx] = h;
    lo[idx] = __float2bfloat16(x - __bfloat162float(h));
}

// ---------------- small utility kernels ----------------
__global__ void fill_kernel(float* __restrict__ p, int n4, float v) {
    int i = blockIdx.x * blockDim.x + threadIdx.x;
    if (i < n4) *(float4*)(p + (size_t)i * 4) = make_float4(v, v, v, v);
}
__global__ void init_conn_kernel(float* __restrict__ p, const float* __restrict__ feat) {
    int i = blockIdx.x * blockDim.x + threadIdx.x;
    if (i < N_CONN * D128) {
        int r = i >> 7, c = i & 127;
        p[i] = (c < NFEAT) ? feat[r * NFEAT + c] : 0.f;
    }
}
__global__ void count_kernel(const int* __restrict__ dst, float* __restrict__ cnt, int e) {
    int i = blockIdx.x * blockDim.x + threadIdx.x;
    if (i < e) atomicAdd(cnt + dst[i], 1.f);
}
__global__ void recip_kernel(float* __restrict__ c, int n) {
    int i = blockIdx.x * blockDim.x + threadIdx.x;
    if (i < n) c[i] = 1.f / fmaxf(c[i], 1.f);
}

// ---------------- edge message + scatter-add ----------------
__global__ void edge_msg_kernel(
    const int* __restrict__ src, const int* __restrict__ dst,
    const float* __restrict__ XS, const float* __restrict__ XD,
    const float* __restrict__ bias, float* __restrict__ out_sum, int e)
{
    int gw = (blockIdx.x * blockDim.x + threadIdx.x) >> 5;
    if (gw >= e) return;
    int lane = threadIdx.x & 31;
    int s = __ldg(src + gw);
    int d = __ldg(dst + gw);
    int c = lane << 2;
    float4 a = *(const float4*)(XS + (size_t)s * 128 + c);
    float4 b = *(const float4*)(XD + (size_t)d * 128 + c);
    float4 bb = *(const float4*)(bias + c);
    float4 m;
    m.x = fmaxf(a.x + b.x + bb.x, 0.f);
    m.y = fmaxf(a.y + b.y + bb.y, 0.f);
    m.z = fmaxf(a.z + b.z + bb.z, 0.f);
    m.w = fmaxf(a.w + b.w + bb.w, 0.f);
    float* p = out_sum + (size_t)d * 128 + c;
    atomicAdd(p + 0, m.x);
    atomicAdd(p + 1, m.y);
    atomicAdd(p + 2, m.z);
    atomicAdd(p + 3, m.w);
}

// ---------------- GRU gate fusion ----------------
__device__ __forceinline__ float gru1(float xz, float hz, float xr, float hr,
                                      float xh, float hh, float h) {
    float z = 1.f / (1.f + expf(-(xz + hz)));
    float r = 1.f / (1.f + expf(-(xr + hr)));
    float c = tanhf(xh + r * hh);
    return z * h + (1.f - z) * c;
}
__global__ void gru_gate_kernel(float* __restrict__ h, const float* __restrict__ xm,
                                const float* __restrict__ hm, int M)
{
    int idx = blockIdx.x * blockDim.x + threadIdx.x;
    if (idx >= M * 32) return;
    int row = idx >> 5;
    int c = (idx & 31) << 2;
    const float* x = xm + (size_t)row * 384;
    const float* hh = hm + (size_t)row * 384;
    float4 xz = *(const float4*)(x + c);
    float4 xr = *(const float4*)(x + 128 + c);
    float4 xh = *(const float4*)(x + 256 + c);
    float4 hz = *(const float4*)(hh + c);
    float4 hr = *(const float4*)(hh + 128 + c);
    float4 hc = *(const float4*)(hh + 256 + c);
    float* hp = h + (size_t)row * 128 + c;
    float4 hv = *(const float4*)hp;
    float4 o;
    o.x = gru1(xz.x, hz.x, xr.x, hr.x, xh.x, hc.x, hv.x);
    o.y = gru1(xz.y, hz.y, xr.y, hr.y, xh.y, hc.y, hv.y);
    o.z = gru1(xz.z, hz.z, xr.z, hr.z, xh.z, hc.z, hv.z);
    o.w = gru1(xz.w, hz.w, xr.w, hr.w, xh.w, hc.w, hv.w);
    *(float4*)hp = o;
}

// ---------------- readout tail ----------------
__global__ void readout_kernel(const float* __restrict__ H2, const float* __restrict__ W3,
                               const float* __restrict__ b3, float* __restrict__ out, int M)
{
    __shared__ float w[64 * 15];
    __shared__ float bb[15];
    for (int i = threadIdx.x; i < 64 * 15; i += blockDim.x) w[i] = W3[i];
    if (threadIdx.x < 15) bb[threadIdx.x] = b3[threadIdx.x];
    __syncthreads();
    int row = blockIdx.x * blockDim.x + threadIdx.x;
    if (row >= M) return;
    float acc[15];
#pragma unroll
    for (int j = 0; j < 15; j++) acc[j] = bb[j];
    const float* hrow = H2 + (size_t)row * 64;
#pragma unroll 16
    for (int k = 0; k < 64; k++) {
        float hv = __ldg(hrow + k);
#pragma unroll
        for (int j = 0; j < 15; j++) acc[j] += hv * w[k * 15 + j];
    }
    float mx = acc[0];
#pragma unroll
    for (int j = 1; j < 15; j++) mx = fmaxf(mx, acc[j]);
    float sum = 0.f;
#pragma unroll
    for (int j = 0; j < 15; j++) { acc[j] = expf(acc[j] - mx); sum += acc[j]; }
    float inv = 1.f / sum;
    float* op = out + (size_t)row * 15;
#pragma unroll
    for (int j = 0; j < 15; j++) op[j] = acc[j] * inv;
}

// ---------------- host side ----------------
static const int SMEM128 = 65536 + 128 * 512;  // 131072
static const int SMEM64  = 65536 + 64 * 512;   // 98304

static inline void launch_mma128(const float* A, const __nv_bfloat16* Bh,
                                 const __nv_bfloat16* Bl, float* C, int M, int Ntot,
                                 const float* bias, const float* rs, int relu) {
    dim3 g((M + 127) / 128, Ntot / 128);
    mma_gemm<128><<<g, 256, SMEM128>>>(A, Bh, Bl, C, M, Ntot, bias, rs, relu);
}
static inline void launch_mma64(const float* A, const __nv_bfloat16* Bh,
                                const __nv_bfloat16* Bl, float* C, int M,
                                const float* bias, int relu) {
    dim3 g((M + 127) / 128, 1);
    mma_gemm<64><<<g, 256, SMEM64>>>(A, Bh, Bl, C, M, 64, bias, nullptr, relu);
}
static inline void launch_zero(float* p, int n) {
    int n4 = n >> 2;
    fill_kernel<<<(n4 + 255) / 256, 256>>>(p, n4, 0.f);
}

extern "C" void kernel_launch(void* const* d_in, const int* in_sizes, int n_in,
                              void* d_out, int out_size)
{
    const float* feat  = (const float*)d_in[0];
    const int*   s_i2c = (const int*)d_in[1];
    const int*   d_i2c = (const int*)d_in[2];
    const int*   s_c2i = (const int*)d_in[3];
    const int*   d_c2i = (const int*)d_in[4];
    const float* W_m1  = (const float*)d_in[5];
    const float* b_m1  = (const float*)d_in[6];
    const float* W_m2  = (const float*)d_in[7];
    const float* b_m2  = (const float*)d_in[8];
    const float* gik   = (const float*)d_in[9];
    const float* gir   = (const float*)d_in[10];
    const float* gib   = (const float*)d_in[11];
    const float* gck   = (const float*)d_in[12];
    const float* gcr   = (const float*)d_in[13];
    const float* gcb   = (const float*)d_in[14];
    const float* Wr1   = (const float*)d_in[15];
    const float* br1   = (const float*)d_in[16];
    const float* Wr2   = (const float*)d_in[17];
    const float* br2   = (const float*)d_in[18];
    const float* Wr3   = (const float*)d_in[19];
    const float* br3   = (const float*)d_in[20];
    float* out = (float*)d_out;

    cudaFuncSetAttribute(mma_gemm<128>, cudaFuncAttributeMaxDynamicSharedMemorySize, SMEM128);
    cudaFuncSetAttribute(mma_gemm<64>,  cudaFuncAttributeMaxDynamicSharedMemorySize, SMEM64);

    void* p;
    cudaGetSymbolAddress(&p, g_ip);       float* ip       = (float*)p;
    cudaGetSymbolAddress(&p, g_conn);     float* conn     = (float*)p;
    cudaGetSymbolAddress(&p, g_XA);       float* XA       = (float*)p;
    cudaGetSymbolAddress(&p, g_XB);       float* XB       = (float*)p;
    cudaGetSymbolAddress(&p, g_YA);       float* YA       = (float*)p;
    cudaGetSymbolAddress(&p, g_YB);       float* YB       = (float*)p;
    cudaGetSymbolAddress(&p, g_agg_conn); float* agg_conn = (float*)p;
    cudaGetSymbolAddress(&p, g_agg_ip);   float* agg_ip   = (float*)p;
    cudaGetSymbolAddress(&p, g_xm_ip);    float* xm_ip    = (float*)p;
    cudaGetSymbolAddress(&p, g_hm_ip);    float* hm_ip    = (float*)p;
    cudaGetSymbolAddress(&p, g_xm_c);     float* xm_c     = (float*)p;
    cudaGetSymbolAddress(&p, g_hm_c);     float* hm_c     = (float*)p;
    cudaGetSymbolAddress(&p, g_rc_conn);  float* rc_conn  = (float*)p;
    cudaGetSymbolAddress(&p, g_rc_ip);    float* rc_ip    = (float*)p;
    cudaGetSymbolAddress(&p, g_H1);       float* H1       = (float*)p;
    cudaGetSymbolAddress(&p, g_H2);       float* H2       = (float*)p;

    __nv_bfloat16 *m1t_h, *m1t_l, *m1b_h, *m1b_l, *m2t_h, *m2t_l, *m2b_h, *m2b_l;
    __nv_bfloat16 *gik_h, *gik_l, *gir_h, *gir_l, *gck_h, *gck_l, *gcr_h, *gcr_l;
    __nv_bfloat16 *wr1_h, *wr1_l, *wr2_h, *wr2_l;
    cudaGetSymbolAddress(&p, g_m1t_h); m1t_h = (__nv_bfloat16*)p;
    cudaGetSymbolAddress(&p, g_m1t_l); m1t_l = (__nv_bfloat16*)p;
    cudaGetSymbolAddress(&p, g_m1b_h); m1b_h = (__nv_bfloat16*)p;
    cudaGetSymbolAddress(&p, g_m1b_l); m1b_l = (__nv_bfloat16*)p;
    cudaGetSymbolAddress(&p, g_m2t_h); m2t_h = (__nv_bfloat16*)p;
    cudaGetSymbolAddress(&p, g_m2t_l); m2t_l = (__nv_bfloat16*)p;
    cudaGetSymbolAddress(&p, g_m2b_h); m2b_h = (__nv_bfloat16*)p;
    cudaGetSymbolAddress(&p, g_m2b_l); m2b_l = (__nv_bfloat16*)p;
    cudaGetSymbolAddress(&p, g_gik_h); gik_h = (__nv_bfloat16*)p;
    cudaGetSymbolAddress(&p, g_gik_l); gik_l = (__nv_bfloat16*)p;
    cudaGetSymbolAddress(&p, g_gir_h); gir_h = (__nv_bfloat16*)p;
    cudaGetSymbolAddress(&p, g_gir_l); gir_l = (__nv_bfloat16*)p;
    cudaGetSymbolAddress(&p, g_gck_h); gck_h = (__nv_bfloat16*)p;
    cudaGetSymbolAddress(&p, g_gck_l); gck_l = (__nv_bfloat16*)p;
    cudaGetSymbolAddress(&p, g_gcr_h); gcr_h = (__nv_bfloat16*)p;
    cudaGetSymbolAddress(&p, g_gcr_l); gcr_l = (__nv_bfloat16*)p;
    cudaGetSymbolAddress(&p, g_wr1_h); wr1_h = (__nv_bfloat16*)p;
    cudaGetSymbolAddress(&p, g_wr1_l); wr1_l = (__nv_bfloat16*)p;
    cudaGetSymbolAddress(&p, g_wr2_h); wr2_h = (__nv_bfloat16*)p;
    cudaGetSymbolAddress(&p, g_wr2_l); wr2_l = (__nv_bfloat16*)p;

    // --- weight prep (transpose + bf16 hi/lo split) ---
    prep_weight<<<(128 * 128 + 255) / 256, 256>>>(W_m1, 128, m1t_h, m1t_l);
    prep_weight<<<(128 * 128 + 255) / 256, 256>>>(W_m1 + 128 * 128, 128, m1b_h, m1b_l);
    prep_weight<<<(128 * 128 + 255) / 256, 256>>>(W_m2, 128, m2t_h, m2t_l);
    prep_weight<<<(128 * 128 + 255) / 256, 256>>>(W_m2 + 128 * 128, 128, m2b_h, m2b_l);
    prep_weight<<<(384 * 128 + 255) / 256, 256>>>(gik, 384, gik_h, gik_l);
    prep_weight<<<(384 * 128 + 255) / 256, 256>>>(gir, 384, gir_h, gir_l);
    prep_weight<<<(384 * 128 + 255) / 256, 256>>>(gck, 384, gck_h, gck_l);
    prep_weight<<<(384 * 128 + 255) / 256, 256>>>(gcr, 384, gcr_h, gcr_l);
    prep_weight<<<(128 * 128 + 255) / 256, 256>>>(Wr1, 128, wr1_h, wr1_l);
    prep_weight<<<(64 * 128 + 255) / 256, 256>>>(Wr2, 64, wr2_h, wr2_l);

    // --- segment counts (reciprocals) ---
    launch_zero(rc_conn, N_CONN);
    launch_zero(rc_ip, N_IP);
    count_kernel<<<(N_E + 255) / 256, 256>>>(d_i2c, rc_conn, N_E);
    count_kernel<<<(N_E + 255) / 256, 256>>>(d_c2i, rc_ip, N_E);
    recip_kernel<<<(N_CONN + 255) / 256, 256>>>(rc_conn, N_CONN);
    recip_kernel<<<(N_IP + 255) / 256, 256>>>(rc_ip, N_IP);

    // --- init states ---
    fill_kernel<<<((N_IP * D128 / 4) + 255) / 256, 256>>>(ip, N_IP * D128 / 4, 1.f);
    init_conn_kernel<<<(N_CONN * D128 + 255) / 256, 256>>>(conn, feat);

    const int edge_blocks = (N_E * 32 + 255) / 256;

    for (int t = 0; t < T_ITERS; t++) {
        // per-node halves of the message MLPs (factorized concat-GEMM)
        launch_mma128(ip,   m1t_h, m1t_l, XA, N_IP,   128, nullptr, nullptr, 0);
        launch_mma128(conn, m1b_h, m1b_l, XB, N_CONN, 128, nullptr, nullptr, 0);
        launch_mma128(conn, m2t_h, m2t_l, YA, N_CONN, 128, nullptr, nullptr, 0);
        launch_mma128(ip,   m2b_h, m2b_l, YB, N_IP,   128, nullptr, nullptr, 0);

        launch_zero(agg_conn, N_CONN * D128);
        launch_zero(agg_ip, N_IP * D128);

        edge_msg_kernel<<<edge_blocks, 256>>>(s_i2c, d_i2c, XA, XB, b_m1, agg_conn, N_E);
        edge_msg_kernel<<<edge_blocks, 256>>>(s_c2i, d_c2i, YA, YB, b_m2, agg_ip, N_E);

        // GRU pre-activations (mean folded in via row-scale on the sum)
        launch_mma128(agg_ip,   gik_h, gik_l, xm_ip, N_IP,   384, gib,       rc_ip,   0);
        launch_mma128(ip,       gir_h, gir_l, hm_ip, N_IP,   384, gib + 384, nullptr, 0);
        launch_mma128(agg_conn, gck_h, gck_l, xm_c,  N_CONN, 384, gcb,       rc_conn, 0);
        launch_mma128(conn,     gcr_h, gcr_l, hm_c,  N_CONN, 384, gcb + 384, nullptr, 0);

        gru_gate_kernel<<<(N_IP * 32 + 255) / 256, 256>>>(ip, xm_ip, hm_ip, N_IP);
        gru_gate_kernel<<<(N_CONN * 32 + 255) / 256, 256>>>(conn, xm_c, hm_c, N_CONN);
    }

    // --- readout ---
    launch_mma128(conn, wr1_h, wr1_l, H1, N_CONN, 128, br1, nullptr, 1);
    launch_mma64(H1, wr2_h, wr2_l, H2, N_CONN, br2, 1);
    readout_kernel<<<(N_CONN + 127) / 128, 128>>>(H2, Wr3, br3, out, N_CONN);
}